// round 5
// baseline (speedup 1.0000x reference)
#include <cuda_runtime.h>

#define T_STEPS 2048
#define BATCH   256
#define D_IN    16
#define H1      5
#define H2      50
#define NC      20
#define G1      20    // 4*H1
#define G2      200   // 4*H2

typedef unsigned long long ull;

__device__ __forceinline__ ull pack2(float a, float b) {
    ull r; asm("mov.b64 %0, {%1,%2};" : "=l"(r) : "f"(a), "f"(b)); return r;
}
__device__ __forceinline__ ull ffma2(ull a, ull b, ull c) {
    ull d; asm("fma.rn.f32x2 %0, %1, %2, %3;" : "=l"(d) : "l"(a), "l"(b), "l"(c)); return d;
}
__device__ __forceinline__ float2 unpack2(ull v) {
    float2 f; asm("mov.b64 {%0,%1}, %2;" : "=f"(f.x), "=f"(f.y) : "l"(v)); return f;
}
__device__ __forceinline__ float tanh_fast(float x) {
    float y; asm("tanh.approx.f32 %0, %1;" : "=f"(y) : "f"(x)); return y;
}
__device__ __forceinline__ float sigmoid_fast(float x) {
    return fmaf(0.5f, tanh_fast(0.5f * x), 0.5f);
}

// One block per batch element. 256 threads:
//   tid 0..199   : layer-2 gate threads (one gate row each, weights in registers, f32x2 math)
//   tid 200..219 : layer-1 gate threads
//   tid 240..255 : x prefetch threads
// Update phase: tid 0..49 -> (c2,h2); tid 200..204 -> (c1,h1).
// Pipeline: layer-1 computes h1[k] while layer-2 consumes h1[k-1].
__global__ __launch_bounds__(256, 2)
void lstm_fused_kernel(const float* __restrict__ x,
                       const float* __restrict__ W1ih, const float* __restrict__ W1hh,
                       const float* __restrict__ b1ih, const float* __restrict__ b1hh,
                       const float* __restrict__ W2ih, const float* __restrict__ W2hh,
                       const float* __restrict__ b2ih, const float* __restrict__ b2hh,
                       const float* __restrict__ Wfc,  const float* __restrict__ bfc,
                       float* __restrict__ out)
{
    const int b   = blockIdx.x;
    const int tid = threadIdx.x;

    __shared__ __align__(16) float h2s[52];        // h2 state, padded (13 x ulonglong2-friendly)
    __shared__ __align__(16) float h1buf[2][8];    // h1 double buffer, padded
    __shared__ __align__(16) float xs[2][16];      // x double buffer
    __shared__ float acts2[200];
    __shared__ float acts1[20];

    // Per-thread packed weights:
    //  L2 gate thread (tid<200): w2[0..24] = W2hh row pairs, w2[25] = 0 pad;
    //                            wB[0..3]  = W2ih row pairs (padded with zeros)
    //  L1 gate thread (200..219): w2[0..7] = W1ih row pairs, w2[8..11] = W1hh row pairs (padded)
    ull w2[26];
    ull wB[4];
    float bias = 0.0f;
    float c2 = 0.0f, c1 = 0.0f;

    if (tid < G2) {
        const float2* wr = (const float2*)(W2hh + tid * H2);   // 200B row stride -> 8B aligned
        #pragma unroll
        for (int k = 0; k < 25; k++) { float2 v = wr[k]; w2[k] = pack2(v.x, v.y); }
        w2[25] = 0ull;
        const float* wi = W2ih + tid * H1;
        wB[0] = pack2(wi[0], wi[1]);
        wB[1] = pack2(wi[2], wi[3]);
        wB[2] = pack2(wi[4], 0.0f);
        wB[3] = 0ull;
        bias = b2ih[tid] + b2hh[tid];
    } else if (tid < 200 + G1) {
        const int g = tid - 200;
        const float* wx = W1ih + g * D_IN;
        #pragma unroll
        for (int k = 0; k < 8; k++) w2[k] = pack2(wx[2*k], wx[2*k+1]);
        const float* wh = W1hh + g * H1;
        w2[8]  = pack2(wh[0], wh[1]);
        w2[9]  = pack2(wh[2], wh[3]);
        w2[10] = pack2(wh[4], 0.0f);
        w2[11] = 0ull;
        bias = b1ih[g] + b1hh[g];
    }

    // Zero-init states / padding
    if (tid < 52) h2s[tid] = 0.0f;
    if (tid < 8)  { h1buf[0][tid] = 0.0f; h1buf[1][tid] = 0.0f; }
    const float* xb = x + (size_t)b * T_STEPS * D_IN;
    if (tid < 16) xs[0][tid] = xb[tid];   // x[0]
    __syncthreads();

    for (int k = 0; k <= T_STEPS; k++) {
        const int cur  = k & 1;
        const int prev = (k - 1) & 1;

        // ---- gate phase ----
        if (tid < G2) {
            if (k > 0) {
                ull a0 = pack2(bias, 0.0f), a1 = 0ull, a2 = 0ull, a3 = 0ull;
                const ulonglong2* h2v = (const ulonglong2*)h2s;
                #pragma unroll
                for (int q = 0; q < 13; q += 2) {
                    ulonglong2 v = h2v[q];
                    a0 = ffma2(w2[2*q],   v.x, a0);
                    a1 = ffma2(w2[2*q+1], v.y, a1);
                }
                #pragma unroll
                for (int q = 1; q < 13; q += 2) {
                    ulonglong2 v = h2v[q];
                    a2 = ffma2(w2[2*q],   v.x, a2);
                    a3 = ffma2(w2[2*q+1], v.y, a3);
                }
                const ulonglong2* h1v = (const ulonglong2*)h1buf[prev];
                {
                    ulonglong2 v = h1v[0];
                    a0 = ffma2(wB[0], v.x, a0);
                    a1 = ffma2(wB[1], v.y, a1);
                    v = h1v[1];
                    a2 = ffma2(wB[2], v.x, a2);
                    a3 = ffma2(wB[3], v.y, a3);
                }
                float2 f0 = unpack2(a0), f1 = unpack2(a1), f2 = unpack2(a2), f3 = unpack2(a3);
                float acc = ((f0.x + f0.y) + (f1.x + f1.y)) + ((f2.x + f2.y) + (f3.x + f3.y));
                const int gt = tid / H2;   // 0=i,1=f,2=g,3=o
                acts2[tid] = (gt == 2) ? tanh_fast(acc) : sigmoid_fast(acc);
            }
        } else if (tid < 200 + G1) {
            if (k < T_STEPS) {
                ull a0 = pack2(bias, 0.0f), a1 = 0ull, a2 = 0ull, a3 = 0ull;
                const ulonglong2* xv = (const ulonglong2*)xs[cur];
                #pragma unroll
                for (int q = 0; q < 4; q++) {
                    ulonglong2 v = xv[q];
                    if (q & 1) { a2 = ffma2(w2[2*q], v.x, a2); a3 = ffma2(w2[2*q+1], v.y, a3); }
                    else       { a0 = ffma2(w2[2*q], v.x, a0); a1 = ffma2(w2[2*q+1], v.y, a1); }
                }
                const ulonglong2* h1v = (const ulonglong2*)h1buf[prev];
                {
                    ulonglong2 v = h1v[0];
                    a0 = ffma2(w2[8],  v.x, a0);
                    a1 = ffma2(w2[9],  v.y, a1);
                    v = h1v[1];
                    a2 = ffma2(w2[10], v.x, a2);
                    a3 = ffma2(w2[11], v.y, a3);
                }
                float2 f0 = unpack2(a0), f1 = unpack2(a1), f2 = unpack2(a2), f3 = unpack2(a3);
                float acc = ((f0.x + f0.y) + (f1.x + f1.y)) + ((f2.x + f2.y) + (f3.x + f3.y));
                const int g  = tid - 200;
                const int gt = g / H1;
                acts1[g] = (gt == 2) ? tanh_fast(acc) : sigmoid_fast(acc);
            }
        } else if (tid >= 240) {
            // prefetch x[k+1] into the buffer not read this iteration
            if (k + 1 < T_STEPS) {
                const int j = tid - 240;
                xs[(k + 1) & 1][j] = xb[(size_t)(k + 1) * D_IN + j];
            }
        }
        __syncthreads();

        // ---- update phase ----
        if (tid < H2) {
            if (k > 0) {
                const float gi = acts2[tid];
                const float gf = acts2[50 + tid];
                const float gg = acts2[100 + tid];
                const float go = acts2[150 + tid];
                c2 = gf * c2 + gi * gg;
                h2s[tid] = go * tanh_fast(c2);
            }
        } else if (tid >= 200 && tid < 200 + H1) {
            if (k < T_STEPS) {
                const int j = tid - 200;
                const float gi = acts1[j];
                const float gf = acts1[5 + j];
                const float gg = acts1[10 + j];
                const float go = acts1[15 + j];
                c1 = gf * c1 + gi * gg;
                h1buf[cur][j] = go * tanh_fast(c1);
            }
        }
        __syncthreads();
    }

    // ---- epilogue: result = h2_last @ Wfc.T + bfc ; also emit h2_last ----
    if (tid < NC) {
        float acc = bfc[tid];
        #pragma unroll
        for (int k = 0; k < H2; k++) acc += h2s[k] * Wfc[tid * H2 + k];
        out[b * NC + tid] = acc;
    }
    if (tid >= 32 && tid < 32 + H2) {
        const int j = tid - 32;
        out[BATCH * NC + b * H2 + j] = h2s[j];
    }
}

extern "C" void kernel_launch(void* const* d_in, const int* in_sizes, int n_in,
                              void* d_out, int out_size)
{
    (void)in_sizes; (void)n_in; (void)out_size;
    const float* x    = (const float*)d_in[0];
    const float* W1ih = (const float*)d_in[1];
    const float* W1hh = (const float*)d_in[2];
    const float* b1ih = (const float*)d_in[3];
    const float* b1hh = (const float*)d_in[4];
    const float* W2ih = (const float*)d_in[5];
    const float* W2hh = (const float*)d_in[6];
    const float* b2ih = (const float*)d_in[7];
    const float* b2hh = (const float*)d_in[8];
    const float* Wfc  = (const float*)d_in[9];
    const float* bfc  = (const float*)d_in[10];

    lstm_fused_kernel<<<BATCH, 256>>>(x, W1ih, W1hh, b1ih, b1hh,
                                      W2ih, W2hh, b2ih, b2hh,
                                      Wfc, bfc, (float*)d_out);
}